// round 16
// baseline (speedup 1.0000x reference)
#include <cuda_runtime.h>
#include <cuda_fp16.h>
#include <cstdint>

#define BATCH 8
#define NPTS  4096
#define DDIM  512
#define NT    32            // 4096/128 row tiles
#define GRID_X 272          // sum over ti of ceil((NT-ti)/2)
#define BK    32            // k per chunk (64B rows)
#define NCHUNK 16           // DDIM/BK
#define STAGE_BYTES 24576   // A(128x32) 8KB + B(256x32) 16KB
#define NSTAGE 4
#define SMEM_DYN 98304      // 4*24576; >= 4*4224*4 epilogue buffer (67.6KB)

__device__ __half g_xh[(size_t)BATCH * NPTS * DDIM];
__device__ float g_sq[BATCH * NPTS];
__device__ float g_inv[BATCH * NPTS];

// ---------------------------------------------------------------- prep ----
__global__ void prep_kernel(const float* __restrict__ emb) {
    int row = blockIdx.x;               // b*NPTS + n
    int tid = threadIdx.x;              // 128 threads
    float4 v = ((const float4*)(emb + (size_t)row * DDIM))[tid];

    float s = fmaf(v.x, v.x, fmaf(v.y, v.y, fmaf(v.z, v.z, v.w * v.w)));
    __shared__ float red[4];
#pragma unroll
    for (int o = 16; o > 0; o >>= 1) s += __shfl_down_sync(0xffffffffu, s, o);
    if ((tid & 31) == 0) red[tid >> 5] = s;
    __syncthreads();
    float tot = red[0] + red[1] + red[2] + red[3];

    if (sqrtf(tot) >= 1.f) {            // __proj (faithful; won't trigger here)
        float invn = rsqrtf(tot);
        v.x = v.x * invn - 1e-5f; v.y = v.y * invn - 1e-5f;
        v.z = v.z * invn - 1e-5f; v.w = v.w * invn - 1e-5f;
        float s2 = fmaf(v.x, v.x, fmaf(v.y, v.y, fmaf(v.z, v.z, v.w * v.w)));
#pragma unroll
        for (int o = 16; o > 0; o >>= 1) s2 += __shfl_down_sync(0xffffffffu, s2, o);
        __syncthreads();
        if ((tid & 31) == 0) red[tid >> 5] = s2;
        __syncthreads();
        tot = red[0] + red[1] + red[2] + red[3];
    }

    __half2 p0 = __floats2half2_rn(v.x, v.y);
    __half2 p1 = __floats2half2_rn(v.z, v.w);
    uint2 u;
    u.x = *(uint32_t*)&p0;
    u.y = *(uint32_t*)&p1;
    ((uint2*)(g_xh + (size_t)row * DDIM))[tid] = u;
    if (tid == 0) {
        g_sq[row]  = tot;
        g_inv[row] = 1.f / (1.f - tot);
    }
}

// ------------------------------------------------------------- helpers ----
__device__ __forceinline__ void cp_async16(uint32_t dst, const void* src) {
    asm volatile("cp.async.cg.shared.global [%0], [%1], 16;\n" :: "r"(dst), "l"(src));
}
__device__ __forceinline__ void cp_commit() {
    asm volatile("cp.async.commit_group;\n" ::);
}
template <int N>
__device__ __forceinline__ void cp_wait() {
    asm volatile("cp.async.wait_group %0;\n" :: "n"(N));
}
__device__ __forceinline__ void ldsm_x4(uint32_t& r0, uint32_t& r1,
                                        uint32_t& r2, uint32_t& r3, uint32_t a) {
    asm volatile("ldmatrix.sync.aligned.m8n8.x4.shared.b16 {%0,%1,%2,%3}, [%4];\n"
                 : "=r"(r0), "=r"(r1), "=r"(r2), "=r"(r3) : "r"(a));
}

__device__ __forceinline__ float hyp_dist(float gv, float sa, float sb,
                                          float ia, float ib, bool diag) {
    float d2 = fmaxf(sa + sb - 2.f * gv, 0.f);
    float dn;
    asm("sqrt.approx.f32 %0, %1;" : "=f"(dn) : "f"(d2));
    float t = 2.f * dn * ia * ib;           // arg = 1 + t
    float w;
    asm("sqrt.approx.f32 %0, %1;" : "=f"(w) : "f"(t * (t + 2.f)));  // sqrt(arg^2-1)
    float arg = 1.f + t + w;
    float lg;
    asm("lg2.approx.f32 %0, %1;" : "=f"(lg) : "f"(arg));
    return (t > 0.f && !diag) ? lg * 0.69314718055994531f : 0.f;
}

// ---------------------------------------------------------------- gemm ----
__global__ void __launch_bounds__(256, 2)
gram_dist_kernel(float* __restrict__ out) {
    extern __shared__ __align__(1024) char smem_raw[];
    __shared__ float s_sqi[128], s_invi[128], s_sqj[256], s_invj[256];

    const int b  = blockIdx.y;
    const int bN = b * NPTS;

    // block -> (ti, tj0); covers j-tiles tj0, tj0+1
    int p = blockIdx.x, ti = 0;
    while (p >= ((NT + 1 - ti) >> 1)) { p -= (NT + 1 - ti) >> 1; ++ti; }
    const int tj0 = ti + 2 * p;
    const bool valid1 = (tj0 + 1) < NT;

    const int tid  = threadIdx.x;
    const int warp = tid >> 5;
    const int lane = tid & 31;
    const int g  = lane >> 2;           // 0..7
    const int t2 = (lane & 3) * 2;      // 0,2,4,6
    const int wm = warp & 1;            // 2 m-halves of 64 rows
    const int wn = warp >> 1;           // 4 n-quarters of 64 cols

    const uint32_t sbase0 = (uint32_t)__cvta_generic_to_shared(smem_raw);
    float* stageF = (float*)smem_raw;   // epilogue: 4 x [32][132] floats

    // epilogue params
    if (tid < 128) {
        s_sqi[tid]  = g_sq[bN + ti * 128 + tid];
        s_invi[tid] = g_inv[bN + ti * 128 + tid];
    }
    {
        int jr = tj0 * 128 + tid;
        if (jr >= NPTS) jr -= 128;
        s_sqj[tid]  = g_sq[bN + jr];
        s_invj[tid] = g_inv[bN + jr];
    }

    // --- loader: 1536 16B chunks (A rows 0..127 = 512, B rows 0..255 = 1024) ---
    // 64B rows; conflict-free key: c ^= (row>>1)&3.
    const size_t rowA_g = (size_t)(bN + ti * 128) * DDIM;
    auto load_stage = [&](int s, int k0) {
        uint32_t sb = sbase0 + (uint32_t)s * STAGE_BYTES;
#pragma unroll
        for (int i = 0; i < 6; ++i) {
            int chunk = i * 256 + tid;
            const __half* src;
            uint32_t dst;
            if (chunk < 512) {                 // A tile
                int row = chunk >> 2, c = chunk & 3;
                src = g_xh + rowA_g + (size_t)row * DDIM + k0 + c * 8;
                dst = sb + (uint32_t)(row * 64 + ((c ^ ((row >> 1) & 3)) << 4));
            } else {                           // B tile (256 rows)
                int cid = chunk - 512;
                int row = cid >> 2, c = cid & 3;
                int gr = tj0 * 128 + row;
                if (gr >= NPTS) gr -= 128;     // clamp invalid B1 rows
                src = g_xh + (size_t)(bN + gr) * DDIM + k0 + c * 8;
                dst = sb + (uint32_t)(8192 + row * 64 + ((c ^ ((row >> 1) & 3)) << 4));
            }
            cp_async16(dst, src);
        }
    };

    // per-thread ldmatrix geometry (64B rows)
    const int keyA = ((lane & 15) >> 1) & 3;
    const int keyB = ((lane & 7) >> 1) & 3;
    const int dcA = lane >> 4;
    const int dcB = (lane >> 3) & 1;
    uint32_t aByte[4], bByte[4], cAo[2], cBo[2];
#pragma unroll
    for (int mt = 0; mt < 4; ++mt)
        aByte[mt] = (uint32_t)((wm * 64 + mt * 16 + (lane & 15)) * 64);
#pragma unroll
    for (int pp = 0; pp < 4; ++pp)
        bByte[pp] = (uint32_t)(8192 + (wn * 64 + pp * 16 + (lane & 7) + ((lane >> 4) << 3)) * 64);
#pragma unroll
    for (int ks = 0; ks < 2; ++ks) {
        cAo[ks] = (uint32_t)((((ks * 2) | dcA) ^ keyA) << 4);
        cBo[ks] = (uint32_t)((((ks * 2) | dcB) ^ keyB) << 4);
    }

    uint32_t acc[4][8][2];              // f16x2 accumulators (64 regs)
#pragma unroll
    for (int a = 0; a < 4; ++a)
#pragma unroll
        for (int c = 0; c < 8; ++c) { acc[a][c][0] = 0u; acc[a][c][1] = 0u; }

    load_stage(0, 0);  cp_commit();
    load_stage(1, BK); cp_commit();

    for (int kb = 0; kb < NCHUNK; ++kb) {
        if (kb < NCHUNK - 1) cp_wait<1>(); else cp_wait<0>();
        __syncthreads();                // all warps finished chunk kb-1 reads
        if (kb + 2 < NCHUNK) {          // overwrites stage of kb-2 (safe)
            load_stage((kb + 2) & 3, (kb + 2) * BK);
            cp_commit();
        }

        const uint32_t sb = sbase0 + (uint32_t)((kb & 3) * STAGE_BYTES);
#pragma unroll
        for (int ks = 0; ks < 2; ++ks) {            // 2 k16-steps per chunk
            uint32_t afr[4][4], bfr[8][2];
#pragma unroll
            for (int mt = 0; mt < 4; ++mt)
                ldsm_x4(afr[mt][0], afr[mt][1], afr[mt][2], afr[mt][3],
                        sb + aByte[mt] + cAo[ks]);
#pragma unroll
            for (int pp = 0; pp < 4; ++pp)
                ldsm_x4(bfr[2 * pp][0], bfr[2 * pp][1],
                        bfr[2 * pp + 1][0], bfr[2 * pp + 1][1],
                        sb + bByte[pp] + cBo[ks]);
#pragma unroll
            for (int mt = 0; mt < 4; ++mt)
#pragma unroll
                for (int nt = 0; nt < 8; ++nt) {
                    asm volatile(
                        "mma.sync.aligned.m16n8k16.row.col.f16.f16.f16.f16 "
                        "{%0,%1}, {%2,%3,%4,%5}, {%6,%7}, {%0,%1};\n"
                        : "+r"(acc[mt][nt][0]), "+r"(acc[mt][nt][1])
                        : "r"(afr[mt][0]), "r"(afr[mt][1]),
                          "r"(afr[mt][2]), "r"(afr[mt][3]),
                          "r"(bfr[nt][0]), "r"(bfr[nt][1]));
                }
        }
    }
    __syncthreads();                    // mainloop reads done; stage reuse ok

    // ------ epilogue: two passes; owners compute dist + direct + stage -----
    float* outB = out + (size_t)b * NPTS * NPTS;
    const uint32_t gi0 = (uint32_t)(ti * 128);
    const uint32_t gj0 = (uint32_t)(tj0 * 128);

    for (int it2 = 0; it2 < 2; ++it2) {
        if ((wn >> 1) == it2) {         // owner warps (4 of 8)
#pragma unroll
            for (int mt = 0; mt < 4; ++mt) {
#pragma unroll
                for (int nt = 0; nt < 8; ++nt) {
                    const int cl = wn * 64 + nt * 8 + t2;   // 0..255
                    const int qb = (wn & 1) * 2 + (nt >> 2);
                    const int cg = (nt & 3) * 8 + t2;       // 0..31 in group
                    const bool okst = (cl < 128) || valid1;
                    const uint32_t gj = gj0 + (uint32_t)cl;
                    const float sb0 = s_sqj[cl],     ib0 = s_invj[cl];
                    const float sb1 = s_sqj[cl + 1], ib1 = s_invj[cl + 1];
                    float* tp = stageF + qb * 4224 + cg * 132;
#pragma unroll
                    for (int h = 0; h < 2; ++h) {
                        const int rr = wm * 64 + mt * 16 + g + h * 8;
                        const uint32_t gi = gi0 + (uint32_t)rr;
                        const float sa = s_sqi[rr], ia = s_invi[rr];
                        const __half2 hv = *(const __half2*)&acc[mt][nt][h];
                        const float2 gf = __half22float2(hv);
                        float v0 = hyp_dist(gf.x, sa, sb0, ia, ib0, gi == gj);
                        float v1 = hyp_dist(gf.y, sa, sb1, ia, ib1, gi == gj + 1u);
                        if (okst) {
                            float2 pk; pk.x = v0; pk.y = v1;
                            *(float2*)(outB + (gi * (uint32_t)NPTS + gj)) = pk;
                        }
                        tp[rr] = v0; tp[132 + rr] = v1;
                    }
                }
            }
        }
        __syncthreads();
        // mirror sweep: 4 groups x 32 rows x 128 floats = 4096 float4
#pragma unroll
        for (int it = 0; it < 16; ++it) {
            const int idx = it * 256 + tid;
            const int qb  = idx >> 10;
            const int jc  = it2 * 4 + qb;
            const int tjs = tj0 + (jc >> 2);
            if ((tjs > ti) && ((jc < 4) || valid1)) {
                const int rem = idx & 1023;
                const int row = rem >> 5;
                const int q4  = rem & 31;
                float4 v = *(const float4*)(stageF + qb * 4224 + row * 132 + q4 * 4);
                const uint32_t gj = gj0 + (uint32_t)(jc * 32 + row);
                *(float4*)(outB + (gj * (uint32_t)NPTS + gi0 + (uint32_t)(q4 * 4))) = v;
            }
        }
        __syncthreads();
    }
}

// -------------------------------------------------------------- launch ----
extern "C" void kernel_launch(void* const* d_in, const int* in_sizes, int n_in,
                              void* d_out, int out_size) {
    const float* emb = (const float*)d_in[0];
    float* out = (float*)d_out;

    prep_kernel<<<BATCH * NPTS, 128>>>(emb);

    cudaFuncSetAttribute(gram_dist_kernel,
                         cudaFuncAttributeMaxDynamicSharedMemorySize, SMEM_DYN);
    dim3 grid(GRID_X, BATCH);
    gram_dist_kernel<<<grid, 256, SMEM_DYN>>>(out);
}